// round 7
// baseline (speedup 1.0000x reference)
#include <cuda_runtime.h>
#include <math.h>

// Problem constants
#define NBATCH 16
#define NC1 8
#define NC2 16
#define NM 63
#define NK2 32
#define NF (NM*NK2)  /* 2016 */
#define NPIX 16384   /* 128*128 */

// ---------------- device scratch ----------------
__device__ float2  g_Kf[128*NF];
__device__ float2  g_Ff[128*NF];
__device__ float2  g_Cf[256*NF];
__device__ float   g_u[256*NPIX];
__device__ float   g_v[256*NPIX];
__device__ float2  g_Ey[64*32];
__device__ float2  g_Ex[64*64];
__device__ float2  g_WxT[63*128];
__device__ float2  g_WyT[32*128];
__device__ float   g_MU[NF];
__device__ float   g_MV[NF];
__device__ int     g_I[120], g_J[120];

// ---------------- table init (parallel) ----------------
__global__ void k_init() {
    int tid = blockIdx.x*256 + threadIdx.x;
    int stride = gridDim.x*256;
    for (int idx = tid; idx < 64*32; idx += stride) {
        int y = idx >> 5, k2 = idx & 31;
        float s, c; sincospif(-2.0f * (float)(k2*y) / 64.0f, &s, &c);
        g_Ey[idx] = make_float2(c, s);
    }
    for (int idx = tid; idx < 64*64; idx += stride) {
        int m = idx >> 6, x = idx & 63; int k1 = m - 31;
        float s, c; sincospif(-2.0f * (float)(k1*x) / 64.0f, &s, &c);
        g_Ex[idx] = make_float2(c, s);
    }
    for (int idx = tid; idx < 63*128; idx += stride) {
        int m = idx >> 7, n1 = idx & 127; int k1 = m - 31;
        float s, c; sincospif(2.0f * (float)(k1*n1) / 128.0f, &s, &c);
        g_WxT[idx] = make_float2(c, s);
    }
    for (int idx = tid; idx < 32*128; idx += stride) {
        int k2 = idx >> 7, n2 = idx & 127;
        float s, c; sincospif(2.0f * (float)(k2*n2) / 128.0f, &s, &c);
        float sc = ((k2 == 0) ? 1.0f : 2.0f) * (2.0f / 16384.0f);
        g_WyT[idx] = make_float2(c * sc, s * sc);
    }
    for (int idx = tid; idx < NF; idx += stride) {
        int m = idx >> 5, k2 = idx & 31; int k1 = m - 31;
        float den = (float)(k1*k1 + k2*k2);
        if (den == 0.0f) den = 1.0f;
        g_MU[idx] =  (float)k2 / den;
        g_MV[idx] = -(float)k1 / den;
    }
    for (int p = tid; p < 120; p += stride) {
        int off = p, i = 0, cnt = 15;
        while (off >= cnt) { off -= cnt; i++; cnt--; }
        g_I[p] = i; g_J[p] = i + 1 + off;
    }
}

// ---------------- forward DFT (512 threads; fused D4 symmetrization) ----
__global__ void __launch_bounds__(512) k_fft64(const float* __restrict__ f,
                                               const float* __restrict__ kin) {
    __shared__ float  ss[4096];      // [x][y]
    __shared__ float2 sA[2048];      // [x][k2]
    int ch = blockIdx.x;
    int t = threadIdx.x;
    bool isK = (ch < 128);
    const float* src = isK ? (kin + ch*4096) : (f + (ch-128)*4096);
    for (int i = t; i < 4096; i += 512) ss[i] = src[i];
    __syncthreads();
    if (isK) {
        float rv[8];
        #pragma unroll
        for (int r = 0; r < 8; r++) {
            int idx = t + 512*r;
            int a = idx >> 6, b = idx & 63;
            int na = (64 - a) & 63, nb = (64 - b) & 63;
            rv[r] = (ss[a*64 + b]  + ss[nb*64 + a] + ss[na*64 + nb] + ss[b*64 + na]
                   + ss[b*64 + a]  + ss[a*64 + nb] + ss[nb*64 + na] + ss[na*64 + b]) * 0.125f;
        }
        __syncthreads();
        #pragma unroll
        for (int r = 0; r < 8; r++) ss[t + 512*r] = rv[r];
        __syncthreads();
    }
    int k2 = t & 31, grp = t >> 5;
    {
        float2 acc[4];
        #pragma unroll
        for (int r = 0; r < 4; r++) acc[r] = make_float2(0.f, 0.f);
        for (int y = 0; y < 64; y++) {
            float2 e = g_Ey[y*32 + k2];
            #pragma unroll
            for (int r = 0; r < 4; r++) {
                float sv = ss[(grp*4 + r)*64 + y];
                acc[r].x = fmaf(sv, e.x, acc[r].x);
                acc[r].y = fmaf(sv, e.y, acc[r].y);
            }
        }
        #pragma unroll
        for (int r = 0; r < 4; r++) sA[(grp*4 + r)*32 + k2] = acc[r];
    }
    __syncthreads();
    {
        float2 acc[4];
        #pragma unroll
        for (int r = 0; r < 4; r++) acc[r] = make_float2(0.f, 0.f);
        for (int x = 0; x < 64; x++) {
            #pragma unroll
            for (int r = 0; r < 4; r++) {
                int m = grp*4 + r;
                float2 e = g_Ex[m*64 + x];
                float2 a = sA[x*32 + k2];
                acc[r].x = fmaf(e.x, a.x, fmaf(-e.y, a.y, acc[r].x));
                acc[r].y = fmaf(e.x, a.y, fmaf( e.y, a.x, acc[r].y));
            }
        }
        float2* dstF = isK ? (g_Kf + ch*NF) : (g_Ff + (ch-128)*NF);
        #pragma unroll
        for (int r = 0; r < 4; r++) {
            int m = grp*4 + r;
            if (m < 63) dstF[m*32 + k2] = acc[r];
        }
    }
}

// ---------------- channel contraction ----------------
__global__ void k_conv() {
    int idx = blockIdx.x * 256 + threadIdx.x;
    int mk = idx % NF;
    int bj = idx / NF;
    int b = bj >> 4, j = bj & 15;
    float2 acc = make_float2(0.f, 0.f);
    #pragma unroll
    for (int i = 0; i < 8; i++) {
        float2 Fv = g_Ff[(b*8 + i)*NF + mk];
        float2 Kv = g_Kf[(i*16 + j)*NF + mk];
        acc.x = fmaf(Fv.x, Kv.x, fmaf(-Fv.y, Kv.y, acc.x));
        acc.y = fmaf(Fv.x, Kv.y, fmaf( Fv.y, Kv.x, acc.y));
    }
    g_Cf[bj*NF + mk] = acc;
}

// ---------------- fused inverse transform: quarter-channel blocks ----------
// grid = 640 ch * 4 quarters, 128 threads, 6 CTA/SM.
// Quarter qt handles n1h in [qt*16, qt*16+16) and mirrors (32 output rows);
// qt==0 additionally handles output row n1=64.
// smem: SD[31*32] float4 (15872 B) + Zs[32] float2 (256 B) + Qs[32*34] float2 (8704 B)
#define SM2_SD   0
#define SM2_Z    15872
#define SM2_Q    16128
#define SM2_TOT  (16128 + 8704)

__global__ void __launch_bounds__(128, 6) k_itrans(float* __restrict__ out) {
    extern __shared__ char sm[];
    float4* SD = (float4*)(sm + SM2_SD);      // [(k1-1)*32 + k2] = (Sr,Si,Dr,Di)
    float2* Zs = (float2*)(sm + SM2_Z);       // k1=0 row
    float2* Qs = (float2*)(sm + SM2_Q);       // [k2*34 + j], j<16: n1h, 16..31: mirror, 32: n1=64

    int t = threadIdx.x;
    int ch = blockIdx.x >> 2, qt = blockIdx.x & 3;
    const float2* src; float* dst; const float* mul = nullptr; float msgn = 1.0f;
    if (ch < 128) {
        src = g_Ff + ch*NF;
        int b = ch >> 3, c = ch & 7;
        dst = out + (size_t)(b*128 + c) * NPIX;
    } else if (ch < 384) {
        int c2 = ch - 128; src = g_Cf + c2*NF; dst = g_u + (size_t)c2*NPIX; mul = g_MU;  // symmetric in k1
    } else {
        int c2 = ch - 384; src = g_Cf + c2*NF; dst = g_v + (size_t)c2*NPIX; mul = g_MV; msgn = -1.0f;  // antisym
    }

    // phase 1: build S/D directly from global (mul folded; mul(-k1) = msgn*mul(+k1))
    for (int e = t; e < 992; e += 128) {
        int k1 = (e >> 5) + 1, k2 = e & 31;
        float2 gp = src[(31 + k1)*32 + k2];
        float2 gm = src[(31 - k1)*32 + k2];
        float2 a, b;
        if (mul) {
            float m = mul[(31 + k1)*32 + k2];
            a = make_float2(-m*gp.y, m*gp.x);
            float mm = msgn * m;
            b = make_float2(-mm*gm.y, mm*gm.x);
        } else {
            a = gp; b = gm;
        }
        SD[e] = make_float4(a.x + b.x, a.y + b.y, a.x - b.x, a.y - b.y);
    }
    if (t < 32) {
        float2 z = src[31*32 + t];
        if (mul) {
            float m = mul[31*32 + t];
            z = make_float2(-m*z.y, m*z.x);
        }
        Zs[t] = z;
    }
    __syncthreads();

    // phase 2a: Q[k2][64] (only qt==0 needs it; cos = (-1)^k1, sin = 0)
    if (qt == 0 && t < 32) {
        float2 z = Zs[t];
        float pr = z.x, pi = z.y;
        #pragma unroll
        for (int k1 = 1; k1 < 32; k1++) {
            float4 sd = SD[(k1-1)*32 + t];
            float sgn = (k1 & 1) ? -1.0f : 1.0f;
            pr = fmaf(sgn, sd.x, pr);
            pi = fmaf(sgn, sd.y, pi);
        }
        Qs[t*34 + 32] = make_float2(pr, pi);
    }

    // phase 2b: stage1 — n1 = qt*16 + (t&15), 4 k2 per thread (kg = t>>4)
    {
        int jl = t & 15, kg = t >> 4;
        int n1 = qt*16 + jl, k2b = kg*4;
        float P[4], R[4], T[4], U[4];
        #pragma unroll
        for (int u = 0; u < 4; u++) { P[u]=0.f; R[u]=0.f; T[u]=0.f; U[u]=0.f; }
        #pragma unroll 1
        for (int k1 = 1; k1 < 32; k1++) {
            float2 w = g_WxT[(31 + k1)*128 + n1];
            float4 sd[4];
            #pragma unroll
            for (int u = 0; u < 4; u++) sd[u] = SD[(k1-1)*32 + k2b + u];
            #pragma unroll
            for (int u = 0; u < 4; u++) {
                P[u] = fmaf(w.x, sd[u].x, P[u]);
                T[u] = fmaf(w.x, sd[u].y, T[u]);
                U[u] = fmaf(w.y, sd[u].z, U[u]);
                R[u] = fmaf(w.y, sd[u].w, R[u]);
            }
        }
        #pragma unroll
        for (int u = 0; u < 4; u++) {
            int k2 = k2b + u;
            float2 z = Zs[k2];
            Qs[k2*34 + jl]      = make_float2(z.x + P[u] - R[u], z.y + T[u] + U[u]);
            Qs[k2*34 + 16 + jl] = make_float2(z.x + P[u] + R[u], z.y + T[u] - U[u]);
        }
    }
    __syncthreads();

    // row index for local j: j<16 -> qt*16+j ; 16<=j<32 -> (128 - (qt*16 + j-16)) & 127
    // phase 3a: n2 = 64 column for this block's rows (+ row 64 center for qt 0)
    if (t < 32) {
        int j = t;
        int n1row = (j < 16) ? (qt*16 + j) : ((128 - (qt*16 + j - 16)) & 127);
        float acc = 0.f;
        #pragma unroll
        for (int k2 = 0; k2 < 32; k2++)
            acc = fmaf(g_WyT[k2*128 + 64].x, Qs[k2*34 + j].x, acc);
        dst[n1row*128 + 64] = acc;
    } else if (qt == 0 && t == 32) {
        float acc = 0.f;
        #pragma unroll
        for (int k2 = 0; k2 < 32; k2++)
            acc = fmaf(g_WyT[k2*128 + 64].x, Qs[k2*34 + 32].x, acc);
        dst[64*128 + 64] = acc;
    }

    // phase 3b: stage2 — tx = n2 group (4 cols in 0..63), ty = row group (4 rows)
    {
        int tx = t & 15, ty = t >> 4;
        int jb = ty*4;
        float E[4][4], O[4][4];
        #pragma unroll
        for (int u = 0; u < 4; u++)
            #pragma unroll
            for (int j = 0; j < 4; j++) { E[u][j] = 0.f; O[u][j] = 0.f; }
        #pragma unroll 2
        for (int k2 = 0; k2 < 32; k2++) {
            float4 wa = *(const float4*)&g_WyT[k2*128 + tx*4];
            float4 wb = *(const float4*)&g_WyT[k2*128 + tx*4 + 2];
            float2 q[4];
            #pragma unroll
            for (int u = 0; u < 4; u++) q[u] = Qs[k2*34 + jb + u];
            #pragma unroll
            for (int u = 0; u < 4; u++) {
                E[u][0] = fmaf(q[u].x, wa.x, E[u][0]);  O[u][0] = fmaf(q[u].y, wa.y, O[u][0]);
                E[u][1] = fmaf(q[u].x, wa.z, E[u][1]);  O[u][1] = fmaf(q[u].y, wa.w, O[u][1]);
                E[u][2] = fmaf(q[u].x, wb.x, E[u][2]);  O[u][2] = fmaf(q[u].y, wb.y, O[u][2]);
                E[u][3] = fmaf(q[u].x, wb.z, E[u][3]);  O[u][3] = fmaf(q[u].y, wb.w, O[u][3]);
            }
        }
        #pragma unroll
        for (int u = 0; u < 4; u++) {
            int j = jb + u;
            int n1row = (j < 16) ? (qt*16 + j) : ((128 - (qt*16 + j - 16)) & 127);
            float* row = dst + n1row*128;
            *(float4*)(row + tx*4) = make_float4(E[u][0]-O[u][0], E[u][1]-O[u][1],
                                                 E[u][2]-O[u][2], E[u][3]-O[u][3]);
            #pragma unroll
            for (int jj = 0; jj < 4; jj++)
                row[(128 - (tx*4 + jj)) & 127] = E[u][jj] + O[u][jj];
        }
    }

    // phase 3c: output row n1 = 64 (qt==0 only), direct formula (its own mirror)
    if (qt == 0) {
        int n2 = t;
        float acc = 0.f;
        #pragma unroll 4
        for (int k2 = 0; k2 < 32; k2++) {
            float2 q = Qs[k2*34 + 32];
            float2 w = g_WyT[k2*128 + n2];
            acc = fmaf(q.x, w.x, fmaf(-q.y, w.y, acc));
        }
        if (n2 != 64) dst[64*128 + n2] = acc;   // n2=64 done in 3a
    }
}

// ---------------- cross products (vectorized stores) ----------------
__global__ void __launch_bounds__(128) k_cross(float* __restrict__ out) {
    __shared__ float us[16*128], vs[16*128];
    int b = blockIdx.x >> 7, n1 = blockIdx.x & 127;
    int t = threadIdx.x;
    for (int i = t; i < 16*128; i += 128) {
        int c = i >> 7, n2 = i & 127;
        us[i] = g_u[((size_t)(b*16 + c)*128 + n1)*128 + n2];
        vs[i] = g_v[((size_t)(b*16 + c)*128 + n1)*128 + n2];
    }
    __syncthreads();
    int q = t & 31, g = t >> 5;
    float* obase = out + ((size_t)b*128 + 8)*NPIX + n1*128 + q*4;
    #pragma unroll 2
    for (int pp = 0; pp < 30; pp++) {
        int p = g*30 + pp;
        int i = g_I[p], j = g_J[p];
        float4 ui = *(float4*)&us[i*128 + q*4];
        float4 vj = *(float4*)&vs[j*128 + q*4];
        float4 uj = *(float4*)&us[j*128 + q*4];
        float4 vi = *(float4*)&vs[i*128 + q*4];
        float4 r;
        r.x = ui.x*vj.x - uj.x*vi.x;
        r.y = ui.y*vj.y - uj.y*vi.y;
        r.z = ui.z*vj.z - uj.z*vi.z;
        r.w = ui.w*vj.w - uj.w*vi.w;
        *(float4*)(obase + (size_t)p*NPIX) = r;
    }
}

// ---------------- launch ----------------
extern "C" void kernel_launch(void* const* d_in, const int* in_sizes, int n_in,
                              void* d_out, int out_size) {
    const float* f    = (const float*)d_in[0];   // [16,8,64,64]
    const float* kern = (const float*)d_in[1];   // [1,8,16,64,64]
    float* out = (float*)d_out;                  // [16,128,128,128]
    (void)in_sizes; (void)n_in; (void)out_size;

    cudaFuncSetAttribute(k_itrans, cudaFuncAttributeMaxDynamicSharedMemorySize, SM2_TOT);

    k_init   <<<40,   256>>>();
    k_fft64  <<<256,  512>>>(f, kern);
    k_conv   <<<2016, 256>>>();
    k_itrans <<<2560, 128, SM2_TOT>>>(out);
    k_cross  <<<2048, 128>>>(out);
}

// round 8
// speedup vs baseline: 1.0642x; 1.0642x over previous
#include <cuda_runtime.h>
#include <math.h>

// Problem constants
#define NBATCH 16
#define NC1 8
#define NC2 16
#define NM 63
#define NK2 32
#define NF (NM*NK2)  /* 2016 */
#define NPIX 16384   /* 128*128 */

// ---------------- device scratch ----------------
__device__ float2  g_Kf[128*NF];
__device__ float2  g_Ff[128*NF];
__device__ float2  g_Cf[256*NF];
__device__ float   g_u[256*NPIX];
__device__ float   g_v[256*NPIX];
__device__ float2  g_Ey[64*32];
__device__ float2  g_Ex[64*64];
__device__ float2  g_WxT[63*128];
__device__ float2  g_WyT[32*128];
__device__ float   g_MU[NF];
__device__ float   g_MV[NF];
__device__ int     g_I[120], g_J[120];

// ---------------- table init (parallel) ----------------
__global__ void k_init() {
    int tid = blockIdx.x*256 + threadIdx.x;
    int stride = gridDim.x*256;
    for (int idx = tid; idx < 64*32; idx += stride) {
        int y = idx >> 5, k2 = idx & 31;
        float s, c; sincospif(-2.0f * (float)(k2*y) / 64.0f, &s, &c);
        g_Ey[idx] = make_float2(c, s);
    }
    for (int idx = tid; idx < 64*64; idx += stride) {
        int m = idx >> 6, x = idx & 63; int k1 = m - 31;
        float s, c; sincospif(-2.0f * (float)(k1*x) / 64.0f, &s, &c);
        g_Ex[idx] = make_float2(c, s);
    }
    for (int idx = tid; idx < 63*128; idx += stride) {
        int m = idx >> 7, n1 = idx & 127; int k1 = m - 31;
        float s, c; sincospif(2.0f * (float)(k1*n1) / 128.0f, &s, &c);
        g_WxT[idx] = make_float2(c, s);
    }
    for (int idx = tid; idx < 32*128; idx += stride) {
        int k2 = idx >> 7, n2 = idx & 127;
        float s, c; sincospif(2.0f * (float)(k2*n2) / 128.0f, &s, &c);
        float sc = ((k2 == 0) ? 1.0f : 2.0f) * (2.0f / 16384.0f);
        g_WyT[idx] = make_float2(c * sc, s * sc);
    }
    for (int idx = tid; idx < NF; idx += stride) {
        int m = idx >> 5, k2 = idx & 31; int k1 = m - 31;
        float den = (float)(k1*k1 + k2*k2);
        if (den == 0.0f) den = 1.0f;
        g_MU[idx] =  (float)k2 / den;
        g_MV[idx] = -(float)k1 / den;
    }
    for (int p = tid; p < 120; p += stride) {
        int off = p, i = 0, cnt = 15;
        while (off >= cnt) { off -= cnt; i++; cnt--; }
        g_I[p] = i; g_J[p] = i + 1 + off;
    }
}

// ---------------- forward DFT (512 threads; fused D4 symmetrization) ----
__global__ void __launch_bounds__(512) k_fft64(const float* __restrict__ f,
                                               const float* __restrict__ kin) {
    __shared__ float  ss[4096];
    __shared__ float2 sA[2048];
    int ch = blockIdx.x;
    int t = threadIdx.x;
    bool isK = (ch < 128);
    const float* src = isK ? (kin + ch*4096) : (f + (ch-128)*4096);
    for (int i = t; i < 4096; i += 512) ss[i] = src[i];
    __syncthreads();
    if (isK) {
        float rv[8];
        #pragma unroll
        for (int r = 0; r < 8; r++) {
            int idx = t + 512*r;
            int a = idx >> 6, b = idx & 63;
            int na = (64 - a) & 63, nb = (64 - b) & 63;
            rv[r] = (ss[a*64 + b]  + ss[nb*64 + a] + ss[na*64 + nb] + ss[b*64 + na]
                   + ss[b*64 + a]  + ss[a*64 + nb] + ss[nb*64 + na] + ss[na*64 + b]) * 0.125f;
        }
        __syncthreads();
        #pragma unroll
        for (int r = 0; r < 8; r++) ss[t + 512*r] = rv[r];
        __syncthreads();
    }
    int k2 = t & 31, grp = t >> 5;
    {
        float2 acc[4];
        #pragma unroll
        for (int r = 0; r < 4; r++) acc[r] = make_float2(0.f, 0.f);
        for (int y = 0; y < 64; y++) {
            float2 e = g_Ey[y*32 + k2];
            #pragma unroll
            for (int r = 0; r < 4; r++) {
                float sv = ss[(grp*4 + r)*64 + y];
                acc[r].x = fmaf(sv, e.x, acc[r].x);
                acc[r].y = fmaf(sv, e.y, acc[r].y);
            }
        }
        #pragma unroll
        for (int r = 0; r < 4; r++) sA[(grp*4 + r)*32 + k2] = acc[r];
    }
    __syncthreads();
    {
        float2 acc[4];
        #pragma unroll
        for (int r = 0; r < 4; r++) acc[r] = make_float2(0.f, 0.f);
        for (int x = 0; x < 64; x++) {
            #pragma unroll
            for (int r = 0; r < 4; r++) {
                int m = grp*4 + r;
                float2 e = g_Ex[m*64 + x];
                float2 a = sA[x*32 + k2];
                acc[r].x = fmaf(e.x, a.x, fmaf(-e.y, a.y, acc[r].x));
                acc[r].y = fmaf(e.x, a.y, fmaf( e.y, a.x, acc[r].y));
            }
        }
        float2* dstF = isK ? (g_Kf + ch*NF) : (g_Ff + (ch-128)*NF);
        #pragma unroll
        for (int r = 0; r < 4; r++) {
            int m = grp*4 + r;
            if (m < 63) dstF[m*32 + k2] = acc[r];
        }
    }
}

// ---------------- channel contraction ----------------
__global__ void k_conv() {
    int idx = blockIdx.x * 256 + threadIdx.x;
    int mk = idx % NF;
    int bj = idx / NF;
    int b = bj >> 4, j = bj & 15;
    float2 acc = make_float2(0.f, 0.f);
    #pragma unroll
    for (int i = 0; i < 8; i++) {
        float2 Fv = g_Ff[(b*8 + i)*NF + mk];
        float2 Kv = g_Kf[(i*16 + j)*NF + mk];
        acc.x = fmaf(Fv.x, Kv.x, fmaf(-Fv.y, Kv.y, acc.x));
        acc.y = fmaf(Fv.x, Kv.y, fmaf( Fv.y, Kv.x, acc.y));
    }
    g_Cf[bj*NF + mk] = acc;
}

// ---------------- fused inverse transform: quarter-channel, pipelined ------
#define SM2_SD   0
#define SM2_Z    15872
#define SM2_Q    16128
#define SM2_TOT  (16128 + 8704)

__global__ void __launch_bounds__(128, 5) k_itrans(float* __restrict__ out) {
    extern __shared__ char sm[];
    float4* SD = (float4*)(sm + SM2_SD);      // [(k1-1)*32 + k2]
    float2* Zs = (float2*)(sm + SM2_Z);
    float2* Qs = (float2*)(sm + SM2_Q);       // [k2*34 + j]

    int t = threadIdx.x;
    int ch = blockIdx.x >> 2, qt = blockIdx.x & 3;
    const float2* src; float* dst; const float* mul = nullptr; float msgn = 1.0f;
    if (ch < 128) {
        src = g_Ff + ch*NF;
        int b = ch >> 3, c = ch & 7;
        dst = out + (size_t)(b*128 + c) * NPIX;
    } else if (ch < 384) {
        int c2 = ch - 128; src = g_Cf + c2*NF; dst = g_u + (size_t)c2*NPIX; mul = g_MU;
    } else {
        int c2 = ch - 384; src = g_Cf + c2*NF; dst = g_v + (size_t)c2*NPIX; mul = g_MV; msgn = -1.0f;
    }

    // phase 1: build S/D from global
    for (int e = t; e < 992; e += 128) {
        int k1 = (e >> 5) + 1, k2 = e & 31;
        float2 gp = src[(31 + k1)*32 + k2];
        float2 gm = src[(31 - k1)*32 + k2];
        float2 a, b;
        if (mul) {
            float m = mul[(31 + k1)*32 + k2];
            a = make_float2(-m*gp.y, m*gp.x);
            float mm = msgn * m;
            b = make_float2(-mm*gm.y, mm*gm.x);
        } else {
            a = gp; b = gm;
        }
        SD[e] = make_float4(a.x + b.x, a.y + b.y, a.x - b.x, a.y - b.y);
    }
    if (t < 32) {
        float2 z = src[31*32 + t];
        if (mul) {
            float m = mul[31*32 + t];
            z = make_float2(-m*z.y, m*z.x);
        }
        Zs[t] = z;
    }
    __syncthreads();

    // phase 2a: Q[k2][n1=64] (qt==0 only)
    if (qt == 0 && t < 32) {
        float2 z = Zs[t];
        float pr = z.x, pi = z.y;
        #pragma unroll
        for (int k1 = 1; k1 < 32; k1++) {
            float4 sd = SD[(k1-1)*32 + t];
            float sgn = (k1 & 1) ? -1.0f : 1.0f;
            pr = fmaf(sgn, sd.x, pr);
            pi = fmaf(sgn, sd.y, pi);
        }
        Qs[t*34 + 32] = make_float2(pr, pi);
    }

    // phase 2b: stage1 — software-pipelined over k1
    {
        int jl = t & 15, kg = t >> 4;
        int n1 = qt*16 + jl, k2b = kg*4;
        float P[4], R[4], T[4], U[4];
        #pragma unroll
        for (int u = 0; u < 4; u++) { P[u]=0.f; R[u]=0.f; T[u]=0.f; U[u]=0.f; }
        float4 s0 = SD[k2b+0], s1 = SD[k2b+1], s2 = SD[k2b+2], s3 = SD[k2b+3];
        float2 w = g_WxT[32*128 + n1];
        #pragma unroll
        for (int k1 = 1; k1 <= 31; k1++) {
            float4 c0 = s0, c1 = s1, c2 = s2, c3 = s3;
            float2 wc = w;
            if (k1 < 31) {
                const float4* p = SD + k1*32 + k2b;
                s0 = p[0]; s1 = p[1]; s2 = p[2]; s3 = p[3];
                w = g_WxT[(32 + k1)*128 + n1];
            }
            P[0]=fmaf(wc.x,c0.x,P[0]); T[0]=fmaf(wc.x,c0.y,T[0]); U[0]=fmaf(wc.y,c0.z,U[0]); R[0]=fmaf(wc.y,c0.w,R[0]);
            P[1]=fmaf(wc.x,c1.x,P[1]); T[1]=fmaf(wc.x,c1.y,T[1]); U[1]=fmaf(wc.y,c1.z,U[1]); R[1]=fmaf(wc.y,c1.w,R[1]);
            P[2]=fmaf(wc.x,c2.x,P[2]); T[2]=fmaf(wc.x,c2.y,T[2]); U[2]=fmaf(wc.y,c2.z,U[2]); R[2]=fmaf(wc.y,c2.w,R[2]);
            P[3]=fmaf(wc.x,c3.x,P[3]); T[3]=fmaf(wc.x,c3.y,T[3]); U[3]=fmaf(wc.y,c3.z,U[3]); R[3]=fmaf(wc.y,c3.w,R[3]);
        }
        #pragma unroll
        for (int u = 0; u < 4; u++) {
            int k2 = k2b + u;
            float2 z = Zs[k2];
            Qs[k2*34 + jl]      = make_float2(z.x + P[u] - R[u], z.y + T[u] + U[u]);
            Qs[k2*34 + 16 + jl] = make_float2(z.x + P[u] + R[u], z.y + T[u] - U[u]);
        }
    }
    __syncthreads();

    // phase 3a: n2 = 64 column
    if (t < 32) {
        int j = t;
        int n1row = (j < 16) ? (qt*16 + j) : ((128 - (qt*16 + j - 16)) & 127);
        float acc = 0.f;
        #pragma unroll
        for (int k2 = 0; k2 < 32; k2++)
            acc = fmaf(g_WyT[k2*128 + 64].x, Qs[k2*34 + j].x, acc);
        dst[n1row*128 + 64] = acc;
    } else if (qt == 0 && t == 32) {
        float acc = 0.f;
        #pragma unroll
        for (int k2 = 0; k2 < 32; k2++)
            acc = fmaf(g_WyT[k2*128 + 64].x, Qs[k2*34 + 32].x, acc);
        dst[64*128 + 64] = acc;
    }

    // phase 3b: stage2 — software-pipelined over k2, float4 Q loads
    {
        int tx = t & 15, ty = t >> 4;
        int jb = ty*4;
        float E[4][4], O[4][4];
        #pragma unroll
        for (int u = 0; u < 4; u++)
            #pragma unroll
            for (int j = 0; j < 4; j++) { E[u][j] = 0.f; O[u][j] = 0.f; }
        float4 q01 = *(const float4*)&Qs[jb];
        float4 q23 = *(const float4*)&Qs[jb + 2];
        float4 wa  = *(const float4*)&g_WyT[tx*4];
        float4 wb  = *(const float4*)&g_WyT[tx*4 + 2];
        #pragma unroll
        for (int k2 = 0; k2 < 32; k2++) {
            float4 qc01 = q01, qc23 = q23, wac = wa, wbc = wb;
            if (k2 < 31) {
                q01 = *(const float4*)&Qs[(k2+1)*34 + jb];
                q23 = *(const float4*)&Qs[(k2+1)*34 + jb + 2];
                wa  = *(const float4*)&g_WyT[(k2+1)*128 + tx*4];
                wb  = *(const float4*)&g_WyT[(k2+1)*128 + tx*4 + 2];
            }
            // rows: q0 = (qc01.x,qc01.y), q1 = (qc01.z,qc01.w), q2 = (qc23.x,qc23.y), q3 = (qc23.z,qc23.w)
            E[0][0]=fmaf(qc01.x,wac.x,E[0][0]); O[0][0]=fmaf(qc01.y,wac.y,O[0][0]);
            E[0][1]=fmaf(qc01.x,wac.z,E[0][1]); O[0][1]=fmaf(qc01.y,wac.w,O[0][1]);
            E[0][2]=fmaf(qc01.x,wbc.x,E[0][2]); O[0][2]=fmaf(qc01.y,wbc.y,O[0][2]);
            E[0][3]=fmaf(qc01.x,wbc.z,E[0][3]); O[0][3]=fmaf(qc01.y,wbc.w,O[0][3]);
            E[1][0]=fmaf(qc01.z,wac.x,E[1][0]); O[1][0]=fmaf(qc01.w,wac.y,O[1][0]);
            E[1][1]=fmaf(qc01.z,wac.z,E[1][1]); O[1][1]=fmaf(qc01.w,wac.w,O[1][1]);
            E[1][2]=fmaf(qc01.z,wbc.x,E[1][2]); O[1][2]=fmaf(qc01.w,wbc.y,O[1][2]);
            E[1][3]=fmaf(qc01.z,wbc.z,E[1][3]); O[1][3]=fmaf(qc01.w,wbc.w,O[1][3]);
            E[2][0]=fmaf(qc23.x,wac.x,E[2][0]); O[2][0]=fmaf(qc23.y,wac.y,O[2][0]);
            E[2][1]=fmaf(qc23.x,wac.z,E[2][1]); O[2][1]=fmaf(qc23.y,wac.w,O[2][1]);
            E[2][2]=fmaf(qc23.x,wbc.x,E[2][2]); O[2][2]=fmaf(qc23.y,wbc.y,O[2][2]);
            E[2][3]=fmaf(qc23.x,wbc.z,E[2][3]); O[2][3]=fmaf(qc23.y,wbc.w,O[2][3]);
            E[3][0]=fmaf(qc23.z,wac.x,E[3][0]); O[3][0]=fmaf(qc23.w,wac.y,O[3][0]);
            E[3][1]=fmaf(qc23.z,wac.z,E[3][1]); O[3][1]=fmaf(qc23.w,wac.w,O[3][1]);
            E[3][2]=fmaf(qc23.z,wbc.x,E[3][2]); O[3][2]=fmaf(qc23.w,wbc.y,O[3][2]);
            E[3][3]=fmaf(qc23.z,wbc.z,E[3][3]); O[3][3]=fmaf(qc23.w,wbc.w,O[3][3]);
        }
        #pragma unroll
        for (int u = 0; u < 4; u++) {
            int j = jb + u;
            int n1row = (j < 16) ? (qt*16 + j) : ((128 - (qt*16 + j - 16)) & 127);
            float* row = dst + n1row*128;
            *(float4*)(row + tx*4) = make_float4(E[u][0]-O[u][0], E[u][1]-O[u][1],
                                                 E[u][2]-O[u][2], E[u][3]-O[u][3]);
            #pragma unroll
            for (int jj = 0; jj < 4; jj++)
                row[(128 - (tx*4 + jj)) & 127] = E[u][jj] + O[u][jj];
        }
    }

    // phase 3c: output row n1 = 64 (qt==0 only)
    if (qt == 0) {
        int n2 = t;
        float acc = 0.f;
        #pragma unroll 4
        for (int k2 = 0; k2 < 32; k2++) {
            float2 q = Qs[k2*34 + 32];
            float2 w = g_WyT[k2*128 + n2];
            acc = fmaf(q.x, w.x, fmaf(-q.y, w.y, acc));
        }
        if (n2 != 64) dst[64*128 + n2] = acc;
    }
}

// ---------------- cross products (vectorized stores) ----------------
__global__ void __launch_bounds__(128) k_cross(float* __restrict__ out) {
    __shared__ float us[16*128], vs[16*128];
    int b = blockIdx.x >> 7, n1 = blockIdx.x & 127;
    int t = threadIdx.x;
    for (int i = t; i < 16*128; i += 128) {
        int c = i >> 7, n2 = i & 127;
        us[i] = g_u[((size_t)(b*16 + c)*128 + n1)*128 + n2];
        vs[i] = g_v[((size_t)(b*16 + c)*128 + n1)*128 + n2];
    }
    __syncthreads();
    int q = t & 31, g = t >> 5;
    float* obase = out + ((size_t)b*128 + 8)*NPIX + n1*128 + q*4;
    #pragma unroll 2
    for (int pp = 0; pp < 30; pp++) {
        int p = g*30 + pp;
        int i = g_I[p], j = g_J[p];
        float4 ui = *(float4*)&us[i*128 + q*4];
        float4 vj = *(float4*)&vs[j*128 + q*4];
        float4 uj = *(float4*)&us[j*128 + q*4];
        float4 vi = *(float4*)&vs[i*128 + q*4];
        float4 r;
        r.x = ui.x*vj.x - uj.x*vi.x;
        r.y = ui.y*vj.y - uj.y*vi.y;
        r.z = ui.z*vj.z - uj.z*vi.z;
        r.w = ui.w*vj.w - uj.w*vi.w;
        *(float4*)(obase + (size_t)p*NPIX) = r;
    }
}

// ---------------- launch ----------------
extern "C" void kernel_launch(void* const* d_in, const int* in_sizes, int n_in,
                              void* d_out, int out_size) {
    const float* f    = (const float*)d_in[0];   // [16,8,64,64]
    const float* kern = (const float*)d_in[1];   // [1,8,16,64,64]
    float* out = (float*)d_out;                  // [16,128,128,128]
    (void)in_sizes; (void)n_in; (void)out_size;

    cudaFuncSetAttribute(k_itrans, cudaFuncAttributeMaxDynamicSharedMemorySize, SM2_TOT);

    k_init   <<<40,   256>>>();
    k_fft64  <<<256,  512>>>(f, kern);
    k_conv   <<<2016, 256>>>();
    k_itrans <<<2560, 128, SM2_TOT>>>(out);
    k_cross  <<<2048, 128>>>(out);
}